// round 7
// baseline (speedup 1.0000x reference)
#include <cuda_runtime.h>
#include <cuda_fp16.h>

#define NN 100000
#define NE 1600000
#define F_IN 128
#define F_HID 64
#define N_CLS 16

// ---------------- device scratch (static; ~52.8 MB, identical footprint to passing R3) ----
__device__ __half2 g_t[NN * 32];      // t = act @ W  (gather source, fp16, 64 vals/row)
__device__ float   g_h[NN * F_HID];   // aggregated activations (fp32)
__device__ float   g_dinv[NN];        // deg^{-1/2} (deg includes self loop)
__device__ int     g_deg[NN];         // in-edge count; zeroed by FINAL agg for next replay
__device__ int     g_off[NN];         // exclusive prefix of g_deg
__device__ int     g_cur[NN];         // bucket cursors (seeded to g_off each call)
__device__ int2    g_epk[NE];         // packed (src, dinv[src] bits) by dst bucket
__device__ int     g_bsum[128];       // scan block sums (98 blocks)

// ---------------- f32x2 helpers (Blackwell packed fp32 FMA) ----------------
__device__ __forceinline__ void ffma2(unsigned long long& d,
                                      unsigned long long a, unsigned long long b) {
    asm("fma.rn.f32x2 %0, %1, %2, %3;" : "=l"(d) : "l"(a), "l"(b), "l"(d));
}
__device__ __forceinline__ unsigned long long packdup(float a) {
    unsigned long long r;
    asm("mov.b64 %0, {%1, %1};" : "=l"(r) : "f"(a));
    return r;
}
__device__ __forceinline__ float2 unpk64(unsigned long long v) {
    float2 f;
    asm("mov.b64 {%0, %1}, %2;" : "=f"(f.x), "=f"(f.y) : "l"(v));
    return f;
}

// ---------------- CSR build ----------------
__global__ void k_count(const int* __restrict__ dst) {
    int i = blockIdx.x * blockDim.x + threadIdx.x;   // exact: 6250*256 == NE
    atomicAdd(&g_deg[dst[i]], 1);
}

__global__ void k_scan1() {
    __shared__ int sh[1024];
    int i = blockIdx.x * 1024 + threadIdx.x;
    int v = (i < NN) ? g_deg[i] : 0;
    sh[threadIdx.x] = v;
    __syncthreads();
    #pragma unroll
    for (int ofs = 1; ofs < 1024; ofs <<= 1) {
        int t = (threadIdx.x >= ofs) ? sh[threadIdx.x - ofs] : 0;
        __syncthreads();
        sh[threadIdx.x] += t;
        __syncthreads();
    }
    if (i < NN) g_off[i] = sh[threadIdx.x] - v;              // exclusive within block
    if (threadIdx.x == 1023) g_bsum[blockIdx.x] = sh[1023];  // block total
}

// fused: every block re-scans the 98 block sums, then finalizes off/cur/dinv.
// Registers + shared only; uniform barriers.
__global__ void k_scan23_dinv(int nb) {
    __shared__ int pref[128];
    __shared__ int wt[4];
    int t = threadIdx.x;
    if (t < 128) {
        int lane = t & 31, w = t >> 5;
        int v = (t < nb) ? g_bsum[t] : 0;
        int xr = v;
        #pragma unroll
        for (int o = 1; o < 32; o <<= 1) {
            int y = __shfl_up_sync(0xffffffffu, xr, o);
            if (lane >= o) xr += y;
        }
        if (lane == 31) wt[w] = xr;          // inclusive warp totals
        pref[t] = xr - v;                    // exclusive within warp
    }
    __syncthreads();
    if (t < 128) {
        int w = t >> 5;
        int add = 0;
        #pragma unroll
        for (int k = 0; k < 4; k++) if (k < w) add += wt[k];
        pref[t] += add;                      // exclusive prefix of bsum
    }
    __syncthreads();
    int i = blockIdx.x * blockDim.x + t;
    if (i < NN) {
        int off = g_off[i] + pref[i >> 10];
        g_off[i] = off;
        g_cur[i] = off;
        g_dinv[i] = rsqrtf((float)(g_deg[i] + 1));   // +1 self loop; always > 0
    }
}

__global__ void k_fill(const int* __restrict__ src, const int* __restrict__ dst) {
    int i = blockIdx.x * blockDim.x + threadIdx.x;   // exact
    int d = dst[i];
    int s = src[i];
    int slot = atomicAdd(&g_cur[d], 1);
    g_epk[slot] = make_int2(s, __float_as_int(g_dinv[s]));
}

// ---------------- GEMM: g_t[n,64](fp16) = A[n,K] @ W[K,64], FFMA2 inner loop ----------------
// (verbatim from the 305 us passing kernel)
template<int K, bool USE_GH>
__global__ __launch_bounds__(256, 2) void k_gemm64(const float* __restrict__ Aext,
                                                   const float* __restrict__ W) {
    const int KC = 16;
    const int XS_STRIDE = 260;
    __shared__ float Xs[KC * XS_STRIDE];
    __shared__ float Ws[KC * 64];

    const float* __restrict__ A = USE_GH ? (const float*)g_h : Aext;

    int tid = threadIdx.x;
    int tx = tid & 7;
    int ty = tid >> 3;
    int nb = blockIdx.x * 256;

    unsigned long long accp[8][4];
    #pragma unroll
    for (int i = 0; i < 8; i++)
        #pragma unroll
        for (int j = 0; j < 4; j++) accp[i][j] = 0ull;

    for (int k0 = 0; k0 < K; k0 += KC) {
        {
            int kk = (tid & 3) * 4;
            #pragma unroll
            for (int r = 0; r < 4; r++) {
                int node = r * 64 + (tid >> 2);
                float4 v = make_float4(0.f, 0.f, 0.f, 0.f);
                int gn = nb + node;
                if (gn < NN) v = *(const float4*)(A + (long)gn * K + k0 + kk);
                Xs[(kk + 0) * XS_STRIDE + node] = v.x;
                Xs[(kk + 1) * XS_STRIDE + node] = v.y;
                Xs[(kk + 2) * XS_STRIDE + node] = v.z;
                Xs[(kk + 3) * XS_STRIDE + node] = v.w;
            }
            int kk2 = tid >> 4;
            int c = (tid & 15) * 4;
            *(float4*)(Ws + kk2 * 64 + c) = *(const float4*)(W + (k0 + kk2) * 64 + c);
        }
        __syncthreads();

        #pragma unroll
        for (int kk = 0; kk < KC; kk++) {
            float4 a0 = *(const float4*)(Xs + kk * XS_STRIDE + ty * 8);
            float4 a1 = *(const float4*)(Xs + kk * XS_STRIDE + ty * 8 + 4);
            ulonglong2 w0 = *(const ulonglong2*)(Ws + kk * 64 + tx * 8);
            ulonglong2 w1 = *(const ulonglong2*)(Ws + kk * 64 + tx * 8 + 4);
            unsigned long long bp[4] = {w0.x, w0.y, w1.x, w1.y};
            float a[8] = {a0.x, a0.y, a0.z, a0.w, a1.x, a1.y, a1.z, a1.w};
            #pragma unroll
            for (int i = 0; i < 8; i++) {
                unsigned long long ad = packdup(a[i]);
                #pragma unroll
                for (int j = 0; j < 4; j++)
                    ffma2(accp[i][j], ad, bp[j]);
            }
        }
        __syncthreads();
    }

    #pragma unroll
    for (int i = 0; i < 8; i++) {
        int gn = nb + ty * 8 + i;
        if (gn < NN) {
            __half2 hh[4];
            #pragma unroll
            for (int j = 0; j < 4; j++) {
                float2 f = unpk64(accp[i][j]);
                hh[j] = __floats2half2_rn(f.x, f.y);
            }
            *(uint4*)(g_t + (long)gn * 32 + tx * 4) = *(uint4*)hh;
        }
    }
}

// ---------------- Aggregation: warp per node, half2 gather, fp32 accumulate ----------------
// h[node] = act( bias + dinv_i * ( sum_s dinv_s * t[s] + dinv_i * t[node] ) )
// FINAL: fuse classifier out[node,16] = h @ Wc + bc, and reset g_deg for next replay
template<int RELU, int FINAL>
__global__ __launch_bounds__(256) void k_agg(const float* __restrict__ bias,
                                             const float* __restrict__ Wc,
                                             const float* __restrict__ bc,
                                             float* __restrict__ out) {
    __shared__ float Wcs[F_HID * N_CLS];
    __shared__ float hs[8][F_HID];
    if (FINAL) {
        for (int i = threadIdx.x; i < F_HID * N_CLS; i += 256) Wcs[i] = Wc[i];
        __syncthreads();
    }

    int w    = threadIdx.x >> 5;
    int lane = threadIdx.x & 31;
    int node = blockIdx.x * 8 + w;      // grid exact: NN/8 blocks

    const __half2* __restrict__ tp = g_t;
    float2 acc = make_float2(0.f, 0.f);

    int row = g_off[node];
    int cnt = g_deg[node];
    if (FINAL && lane == 0) g_deg[node] = 0;   // self-reset for next graph replay

    for (int base = 0; base < cnt; base += 32) {
        int idx = base + lane;
        int2 e = make_int2(0, 0);                      // e.y == 0.0f bits
        if (idx < cnt) e = g_epk[row + idx];
        int m = min(32, cnt - base);
        if (m == 32) {
            #pragma unroll
            for (int j = 0; j < 32; j++) {
                int   sj = __shfl_sync(0xffffffffu, e.x, j);
                float wj = __int_as_float(__shfl_sync(0xffffffffu, e.y, j));
                float2 tv = __half22float2(tp[(long)sj * 32 + lane]);
                acc.x = fmaf(wj, tv.x, acc.x);
                acc.y = fmaf(wj, tv.y, acc.y);
            }
        } else {
            #pragma unroll 4
            for (int j = 0; j < m; j++) {
                int   sj = __shfl_sync(0xffffffffu, e.x, j);
                float wj = __int_as_float(__shfl_sync(0xffffffffu, e.y, j));
                float2 tv = __half22float2(tp[(long)sj * 32 + lane]);
                acc.x = fmaf(wj, tv.x, acc.x);
                acc.y = fmaf(wj, tv.y, acc.y);
            }
        }
    }

    float  di = g_dinv[node];
    float2 ts = __half22float2(tp[(long)node * 32 + lane]);
    float2 bv = ((const float2*)bias)[lane];
    float ox = (acc.x + di * ts.x) * di + bv.x;
    float oy = (acc.y + di * ts.y) * di + bv.y;

    if (FINAL) {
        hs[w][2 * lane]     = ox;
        hs[w][2 * lane + 1] = oy;
        __syncwarp();
        int c  = lane & 15;
        int k0 = (lane >> 4) * 32;
        float s = 0.f;
        #pragma unroll
        for (int k = 0; k < 32; k++)
            s = fmaf(hs[w][k0 + k], Wcs[(k0 + k) * N_CLS + c], s);
        s += __shfl_xor_sync(0xffffffffu, s, 16);
        if (lane < 16) out[(long)node * N_CLS + c] = s + __ldg(bc + c);
    } else {
        if (RELU) { ox = fmaxf(ox, 0.f); oy = fmaxf(oy, 0.f); }
        ((float2*)g_h)[(long)node * 32 + lane] = make_float2(ox, oy);
    }
}

// ---------------- launch ----------------
extern "C" void kernel_launch(void* const* d_in, const int* in_sizes, int n_in,
                              void* d_out, int out_size) {
    (void)in_sizes; (void)n_in; (void)out_size;
    const float* x  = (const float*)d_in[0];
    const int*   ei = (const int*)d_in[1];
    const float* W0 = (const float*)d_in[2];
    const float* b0 = (const float*)d_in[3];
    const float* W1 = (const float*)d_in[4];
    const float* b1 = (const float*)d_in[5];
    const float* W2 = (const float*)d_in[6];
    const float* b2 = (const float*)d_in[7];
    const float* Wc = (const float*)d_in[8];
    const float* bc = (const float*)d_in[9];
    float* out = (float*)d_out;

    const int* src = ei;            // edge_index[0]
    const int* dst = ei + NE;       // edge_index[1]

    int nbE = NE / 256;             // 6250 (exact)
    int nbS = (NN + 1023) / 1024;   // 98
    int nbN = (NN + 255) / 256;     // 391
    int nbG = (NN + 255) / 256;     // 391
    int nbA = NN / 8;               // 12500 (exact)

    // CSR build + normalization (g_deg enters zeroed: BSS on first call,
    // FINAL agg's self-reset on every subsequent replay)
    k_count<<<nbE, 256>>>(dst);
    k_scan1<<<nbS, 1024>>>();
    k_scan23_dinv<<<nbN, 256>>>(nbS);
    k_fill<<<nbE, 256>>>(src, dst);

    // layer 0
    k_gemm64<F_IN, false><<<nbG, 256>>>(x, W0);
    k_agg<1, 0><<<nbA, 256>>>(b0, nullptr, nullptr, nullptr);
    // layer 1
    k_gemm64<F_HID, true><<<nbG, 256>>>(nullptr, W1);
    k_agg<1, 0><<<nbA, 256>>>(b1, nullptr, nullptr, nullptr);
    // layer 2 + fused classifier (+ g_deg reset)
    k_gemm64<F_HID, true><<<nbG, 256>>>(nullptr, W2);
    k_agg<0, 1><<<nbA, 256>>>(b2, Wc, bc, out);
}

// round 9
// speedup vs baseline: 1.0291x; 1.0291x over previous
#include <cuda_runtime.h>
#include <cuda_fp16.h>

#define NN 100000
#define NE 1600000
#define F_IN 128
#define F_HID 64
#define N_CLS 16

// ---------------- device scratch (static; ~52.8 MB, identical footprint to passing R3/R7) --
__device__ __half2 g_t[NN * 32];      // t = act @ W  (gather source, fp16, 64 vals/row)
__device__ float   g_h[NN * F_HID];   // aggregated activations (fp32)
__device__ float   g_dinv[NN];        // deg^{-1/2} (deg includes self loop)
__device__ int     g_deg[NN];         // in-edge count; zeroed by FINAL agg for next replay
__device__ int     g_off[NN];         // exclusive prefix of g_deg
__device__ int     g_cur[NN];         // bucket cursors (seeded to g_off each call)
__device__ int2    g_epk[NE];         // packed (src, dinv[src] bits) by dst bucket
__device__ int     g_bsum[128];       // scan block sums (98 blocks)

// ---------------- f32x2 helpers (Blackwell packed fp32 FMA; known-safe asm) ----------------
__device__ __forceinline__ void ffma2(unsigned long long& d,
                                      unsigned long long a, unsigned long long b) {
    asm("fma.rn.f32x2 %0, %1, %2, %3;" : "=l"(d) : "l"(a), "l"(b), "l"(d));
}
__device__ __forceinline__ unsigned long long packdup(float a) {
    unsigned long long r;
    asm("mov.b64 %0, {%1, %1};" : "=l"(r) : "f"(a));
    return r;
}
__device__ __forceinline__ float2 unpk64(unsigned long long v) {
    float2 f;
    asm("mov.b64 {%0, %1}, %2;" : "=f"(f.x), "=f"(f.y) : "l"(v));
    return f;
}

// ---------------- CSR build ----------------
__global__ void k_count(const int* __restrict__ dst) {
    int i = blockIdx.x * blockDim.x + threadIdx.x;   // exact: 6250*256 == NE
    atomicAdd(&g_deg[dst[i]], 1);
}

__global__ void k_scan1() {
    __shared__ int sh[1024];
    int i = blockIdx.x * 1024 + threadIdx.x;
    int v = (i < NN) ? g_deg[i] : 0;
    sh[threadIdx.x] = v;
    __syncthreads();
    #pragma unroll
    for (int ofs = 1; ofs < 1024; ofs <<= 1) {
        int t = (threadIdx.x >= ofs) ? sh[threadIdx.x - ofs] : 0;
        __syncthreads();
        sh[threadIdx.x] += t;
        __syncthreads();
    }
    if (i < NN) g_off[i] = sh[threadIdx.x] - v;              // exclusive within block
    if (threadIdx.x == 1023) g_bsum[blockIdx.x] = sh[1023];  // block total
}

// fused: every block re-scans the 98 block sums, then finalizes off/cur/dinv.
__global__ void k_scan23_dinv(int nb) {
    __shared__ int pref[128];
    __shared__ int wt[4];
    int t = threadIdx.x;
    if (t < 128) {
        int lane = t & 31, w = t >> 5;
        int v = (t < nb) ? g_bsum[t] : 0;
        int xr = v;
        #pragma unroll
        for (int o = 1; o < 32; o <<= 1) {
            int y = __shfl_up_sync(0xffffffffu, xr, o);
            if (lane >= o) xr += y;
        }
        if (lane == 31) wt[w] = xr;          // inclusive warp totals
        pref[t] = xr - v;                    // exclusive within warp
    }
    __syncthreads();
    if (t < 128) {
        int w = t >> 5;
        int add = 0;
        #pragma unroll
        for (int k = 0; k < 4; k++) if (k < w) add += wt[k];
        pref[t] += add;                      // exclusive prefix of bsum
    }
    __syncthreads();
    int i = blockIdx.x * blockDim.x + t;
    if (i < NN) {
        int off = g_off[i] + pref[i >> 10];
        g_off[i] = off;
        g_cur[i] = off;
        g_dinv[i] = rsqrtf((float)(g_deg[i] + 1));   // +1 self loop; always > 0
    }
}

__global__ void k_fill(const int* __restrict__ src, const int* __restrict__ dst) {
    int i = blockIdx.x * blockDim.x + threadIdx.x;   // exact
    int d = dst[i];
    int s = src[i];
    int slot = atomicAdd(&g_cur[d], 1);
    g_epk[slot] = make_int2(s, __float_as_int(g_dinv[s]));
}

// ---------------- GEMM: g_t[n,64](fp16) = A[n,K] @ W[K,64], FFMA2 inner loop ----------------
// (verbatim from the passing R3/R7 kernel — NO mma.sync, which trips the 128MiB guard)
template<int K, bool USE_GH>
__global__ __launch_bounds__(256, 2) void k_gemm64(const float* __restrict__ Aext,
                                                   const float* __restrict__ W) {
    const int KC = 16;
    const int XS_STRIDE = 260;
    __shared__ float Xs[KC * XS_STRIDE];
    __shared__ float Ws[KC * 64];

    const float* __restrict__ A = USE_GH ? (const float*)g_h : Aext;

    int tid = threadIdx.x;
    int tx = tid & 7;
    int ty = tid >> 3;
    int nb = blockIdx.x * 256;

    unsigned long long accp[8][4];
    #pragma unroll
    for (int i = 0; i < 8; i++)
        #pragma unroll
        for (int j = 0; j < 4; j++) accp[i][j] = 0ull;

    for (int k0 = 0; k0 < K; k0 += KC) {
        {
            int kk = (tid & 3) * 4;
            #pragma unroll
            for (int r = 0; r < 4; r++) {
                int node = r * 64 + (tid >> 2);
                float4 v = make_float4(0.f, 0.f, 0.f, 0.f);
                int gn = nb + node;
                if (gn < NN) v = *(const float4*)(A + (long)gn * K + k0 + kk);
                Xs[(kk + 0) * XS_STRIDE + node] = v.x;
                Xs[(kk + 1) * XS_STRIDE + node] = v.y;
                Xs[(kk + 2) * XS_STRIDE + node] = v.z;
                Xs[(kk + 3) * XS_STRIDE + node] = v.w;
            }
            int kk2 = tid >> 4;
            int c = (tid & 15) * 4;
            *(float4*)(Ws + kk2 * 64 + c) = *(const float4*)(W + (k0 + kk2) * 64 + c);
        }
        __syncthreads();

        #pragma unroll
        for (int kk = 0; kk < KC; kk++) {
            float4 a0 = *(const float4*)(Xs + kk * XS_STRIDE + ty * 8);
            float4 a1 = *(const float4*)(Xs + kk * XS_STRIDE + ty * 8 + 4);
            ulonglong2 w0 = *(const ulonglong2*)(Ws + kk * 64 + tx * 8);
            ulonglong2 w1 = *(const ulonglong2*)(Ws + kk * 64 + tx * 8 + 4);
            unsigned long long bp[4] = {w0.x, w0.y, w1.x, w1.y};
            float a[8] = {a0.x, a0.y, a0.z, a0.w, a1.x, a1.y, a1.z, a1.w};
            #pragma unroll
            for (int i = 0; i < 8; i++) {
                unsigned long long ad = packdup(a[i]);
                #pragma unroll
                for (int j = 0; j < 4; j++)
                    ffma2(accp[i][j], ad, bp[j]);
            }
        }
        __syncthreads();
    }

    #pragma unroll
    for (int i = 0; i < 8; i++) {
        int gn = nb + ty * 8 + i;
        if (gn < NN) {
            __half2 hh[4];
            #pragma unroll
            for (int j = 0; j < 4; j++) {
                float2 f = unpk64(accp[i][j]);
                hh[j] = __floats2half2_rn(f.x, f.y);
            }
            *(uint4*)(g_t + (long)gn * 32 + tx * 4) = *(uint4*)hh;
        }
    }
}

// ---------------- Aggregation: warp per node, smem edge broadcast, fp32 accumulate --------
// h[node] = act( bias + dinv_i * ( sum_s dinv_s * t[s] + dinv_i * t[node] ) )
// FINAL: fuse classifier out[node,16] = h @ Wc + bc, and reset g_deg for next replay
template<int RELU, int FINAL>
__global__ __launch_bounds__(256) void k_agg(const float* __restrict__ bias,
                                             const float* __restrict__ Wc,
                                             const float* __restrict__ bc,
                                             float* __restrict__ out) {
    __shared__ float Wcs[F_HID * N_CLS];
    __shared__ float hs[8][F_HID];
    __shared__ int2  se[8][32];
    if (FINAL) {
        for (int i = threadIdx.x; i < F_HID * N_CLS; i += 256) Wcs[i] = Wc[i];
        __syncthreads();
    }

    int w    = threadIdx.x >> 5;
    int lane = threadIdx.x & 31;
    int node = blockIdx.x * 8 + w;      // grid exact: NN/8 blocks

    const __half2* __restrict__ tp = g_t;
    float2 acc = make_float2(0.f, 0.f);

    int row = g_off[node];
    int cnt = g_deg[node];
    if (FINAL && lane == 0) g_deg[node] = 0;   // self-reset for next graph replay

    for (int base = 0; base < cnt; base += 32) {
        int idx = base + lane;
        int m = min(32, cnt - base);
        if (idx < cnt) se[w][lane] = g_epk[row + idx];
        __syncwarp();
        if (m == 32) {
            #pragma unroll
            for (int j = 0; j < 32; j++) {
                int2 ev = se[w][j];                         // LDS.64 broadcast
                float wj = __int_as_float(ev.y);
                float2 tv = __half22float2(tp[(long)ev.x * 32 + lane]);
                acc.x = fmaf(wj, tv.x, acc.x);
                acc.y = fmaf(wj, tv.y, acc.y);
            }
        } else {
            #pragma unroll 4
            for (int j = 0; j < m; j++) {
                int2 ev = se[w][j];
                float wj = __int_as_float(ev.y);
                float2 tv = __half22float2(tp[(long)ev.x * 32 + lane]);
                acc.x = fmaf(wj, tv.x, acc.x);
                acc.y = fmaf(wj, tv.y, acc.y);
            }
        }
        __syncwarp();
    }

    float  di = g_dinv[node];
    float2 ts = __half22float2(tp[(long)node * 32 + lane]);
    float2 bv = ((const float2*)bias)[lane];
    float ox = (acc.x + di * ts.x) * di + bv.x;
    float oy = (acc.y + di * ts.y) * di + bv.y;

    if (FINAL) {
        hs[w][2 * lane]     = ox;
        hs[w][2 * lane + 1] = oy;
        __syncwarp();
        int c  = lane & 15;
        int k0 = (lane >> 4) * 32;
        float s = 0.f;
        #pragma unroll
        for (int k = 0; k < 32; k++)
            s = fmaf(hs[w][k0 + k], Wcs[(k0 + k) * N_CLS + c], s);
        s += __shfl_xor_sync(0xffffffffu, s, 16);
        if (lane < 16) out[(long)node * N_CLS + c] = s + __ldg(bc + c);
    } else {
        if (RELU) { ox = fmaxf(ox, 0.f); oy = fmaxf(oy, 0.f); }
        ((float2*)g_h)[(long)node * 32 + lane] = make_float2(ox, oy);
    }
}

// ---------------- launch ----------------
extern "C" void kernel_launch(void* const* d_in, const int* in_sizes, int n_in,
                              void* d_out, int out_size) {
    (void)in_sizes; (void)n_in; (void)out_size;
    const float* x  = (const float*)d_in[0];
    const int*   ei = (const int*)d_in[1];
    const float* W0 = (const float*)d_in[2];
    const float* b0 = (const float*)d_in[3];
    const float* W1 = (const float*)d_in[4];
    const float* b1 = (const float*)d_in[5];
    const float* W2 = (const float*)d_in[6];
    const float* b2 = (const float*)d_in[7];
    const float* Wc = (const float*)d_in[8];
    const float* bc = (const float*)d_in[9];
    float* out = (float*)d_out;

    const int* src = ei;            // edge_index[0]
    const int* dst = ei + NE;       // edge_index[1]

    int nbE = NE / 256;             // 6250 (exact)
    int nbS = (NN + 1023) / 1024;   // 98
    int nbN = (NN + 255) / 256;     // 391
    int nbG = (NN + 255) / 256;     // 391
    int nbA = NN / 8;               // 12500 (exact)

    // CSR build + normalization (g_deg enters zeroed: BSS on first call,
    // FINAL agg's self-reset on every subsequent replay)
    k_count<<<nbE, 256>>>(dst);
    k_scan1<<<nbS, 1024>>>();
    k_scan23_dinv<<<nbN, 256>>>(nbS);
    k_fill<<<nbE, 256>>>(src, dst);

    // layer 0
    k_gemm64<F_IN, false><<<nbG, 256>>>(x, W0);
    k_agg<1, 0><<<nbA, 256>>>(b0, nullptr, nullptr, nullptr);
    // layer 1
    k_gemm64<F_HID, true><<<nbG, 256>>>(nullptr, W1);
    k_agg<1, 0><<<nbA, 256>>>(b1, nullptr, nullptr, nullptr);
    // layer 2 + fused classifier (+ g_deg reset)
    k_gemm64<F_HID, true><<<nbG, 256>>>(nullptr, W2);
    k_agg<0, 1><<<nbA, 256>>>(b2, Wc, bc, out);
}